// round 11
// baseline (speedup 1.0000x reference)
#include <cuda_runtime.h>
#include <cuda_fp16.h>

#define BB 32
#define CC 512
#define C8 64
#define NPIX 4096
#define NT 128
#define CT 64
#define CTILES 8
#define NITEMS (BB*(NPIX/NT))   // 1024

#define ROWB 144                 // padded row stride (bytes): conflict-free ldmatrix
#define PLANE (128*ROWB)         // 18432 B per fp16 plane tile
#define SM_X0 0                  // X buffer 0: 2 planes
#define SM_X1 36864              // X buffer 1: 2 planes
#define SMEM_BYTES 73728

typedef unsigned u32;
typedef unsigned long long u64t;
typedef unsigned short u16t;

// ---------------- helpers ----------------
__device__ __forceinline__ u32 smem_u32(const void* p) {
    u32 a; asm("{ .reg .u64 t; cvta.to.shared.u64 t, %1; cvt.u32.u64 %0, t; }" : "=r"(a) : "l"(p));
    return a;
}
__device__ __forceinline__ u64t pack2f(float lo, float hi) {
    u64t r; asm("mov.b64 %0, {%1, %2};" : "=l"(r) : "f"(lo), "f"(hi)); return r;
}
__device__ __forceinline__ u64t fma2(u64t a, u64t b, u64t c) {
    u64t d; asm("fma.rn.f32x2 %0, %1, %2, %3;" : "=l"(d) : "l"(a), "l"(b), "l"(c)); return d;
}
__device__ __forceinline__ void unpack2(u64t v, float& lo, float& hi) {
    asm("mov.b64 {%0, %1}, %2;" : "=f"(lo), "=f"(hi) : "l"(v));
}
__device__ __forceinline__ void ldsm2(u32* r, u32 addr) {
    asm volatile("ldmatrix.sync.aligned.m8n8.x2.shared.b16 {%0,%1}, [%2];"
        : "=r"(r[0]), "=r"(r[1]) : "r"(addr));
}
__device__ __forceinline__ void mma_f16(float* d, const u32* a, const u32* b) {
    asm volatile("mma.sync.aligned.m16n8k16.row.col.f32.f16.f16.f32 "
        "{%0,%1,%2,%3}, {%4,%5,%6,%7}, {%8,%9}, {%0,%1,%2,%3};"
        : "+f"(d[0]), "+f"(d[1]), "+f"(d[2]), "+f"(d[3])
        : "r"(a[0]), "r"(a[1]), "r"(a[2]), "r"(a[3]), "r"(b[0]), "r"(b[1]));
}
__device__ __forceinline__ u32 h2u(__half2 h) { return *reinterpret_cast<u32*>(&h); }

// ---------------- globals (no allocation allowed) ----------------
__device__ float g_logits[BB*C8*C8];
__device__ float g_xsum[BB*CC];
// A-fragment table: frag = ct<<6 | p<<5 | wm<<3 | ks<<1 | mt ; per frag 32 lanes x 16B
__device__ uint4 g_wfrag[512*32];     // 256 KB, L2-resident
__device__ unsigned g_ctr;

// -------------------------------------------------------------------------
// prep: zero accum + build fragment-ordered 2-limb fp16 W table.
// u32 idx decomposition matches kernel read: ((frag*32)+lane)*4 + j
// reg j: row r + (j&1)*8, k + (j>>1)*8 (standard m16n8k16 A layout)
// -------------------------------------------------------------------------
__global__ void prep_kernel(const float* __restrict__ wq,
                            const float* __restrict__ wk) {
    int t = blockIdx.x * blockDim.x + threadIdx.x;
    int S = gridDim.x * blockDim.x;
    if (t == 0) g_ctr = 0;
    for (int i = t; i < BB*C8*C8; i += S) g_logits[i] = 0.f;
    for (int i = t; i < BB*CC;    i += S) g_xsum[i]   = 0.f;
    u32* wf = (u32*)g_wfrag;
    const int total = 512*32*4;
    for (int idx = t; idx < total; idx += S) {
        int j    = idx & 3;
        int lane = (idx >> 2) & 31;
        int frag = idx >> 7;
        int mt = frag & 1;
        int ks = (frag >> 1) & 3;
        int wm = (frag >> 3) & 3;
        int p  = (frag >> 5) & 1;
        int ct = frag >> 6;
        int r    = wm*32 + mt*16 + (lane >> 2) + (j & 1)*8;
        int kloc = ks*16 + (lane & 3)*2 + (j >> 1)*8;
        int c    = ct*64 + kloc;
        float v0 = (r < 64) ? wq[r*CC + c]     : wk[(r-64)*CC + c];
        float v1 = (r < 64) ? wq[r*CC + c + 1] : wk[(r-64)*CC + c + 1];
        __half h0, h1;
        if (p == 0) {
            h0 = __float2half_rn(v0);
            h1 = __float2half_rn(v1);
        } else {
            h0 = __float2half_rn(v0 - __half2float(__float2half_rn(v0)));
            h1 = __float2half_rn(v1 - __half2float(__float2half_rn(v1)));
        }
        __half2 hh = __halves2half2(h0, h1);
        wf[idx] = h2u(hh);
    }
}

// one combo-block: A-frags via LDG.128 from fragment table (prefetch next ks),
// B via ldmatrix from smem. 4 ks x 16 MMAs.
__device__ __forceinline__ void mma_cb_frag(float acc[2][8][4], const uint4* fw,
                                            u32 baseB, const u32* offB, int lane) {
    uint4 fA[2][2];
    fA[0][0] = fw[lane];
    fA[0][1] = fw[32 + lane];
    #pragma unroll
    for (int ks = 0; ks < 4; ks++) {
        const int cur = ks & 1, nxt = cur ^ 1;
        if (ks < 3) {
            fA[nxt][0] = fw[(ks+1)*64 + lane];
            fA[nxt][1] = fw[(ks+1)*64 + 32 + lane];
        }
        #pragma unroll
        for (int h = 0; h < 2; h++) {
            u32 bf[4][2];
            #pragma unroll
            for (int q = 0; q < 4; q++)
                ldsm2(bf[q], baseB + offB[h*4 + q] + ks*32);
            #pragma unroll
            for (int q = 0; q < 4; q++) {
                mma_f16(acc[0][h*4 + q], (const u32*)&fA[cur][0], bf[q]);
                mma_f16(acc[1][h*4 + q], (const u32*)&fA[cur][1], bf[q]);
            }
        }
    }
}

// convert pipeline pieces: each group = 1 pixel column slice (n = g*32+lane), 8 channels
__device__ __forceinline__ void ldg_grp(float* v, const float* xb, int g, int lane) {
    const int n = g*32 + lane;
    #pragma unroll
    for (int j = 0; j < 8; j++) v[j] = xb[(size_t)j*NPIX + n];
}
__device__ __forceinline__ void proc_grp(const float* v, char* xdst, int g, int lane,
                                         int cw, float* csum) {
    const int n = g*32 + lane;
    #pragma unroll
    for (int j = 0; j < 8; j++) csum[j] += v[j];
    __half2 a0 = __floats2half2_rn(v[0], v[1]);
    __half2 a1 = __floats2half2_rn(v[2], v[3]);
    __half2 a2 = __floats2half2_rn(v[4], v[5]);
    __half2 a3 = __floats2half2_rn(v[6], v[7]);
    __half2 b0 = __floats2half2_rn(v[0] - __low2float(a0), v[1] - __high2float(a0));
    __half2 b1 = __floats2half2_rn(v[2] - __low2float(a1), v[3] - __high2float(a1));
    __half2 b2 = __floats2half2_rn(v[4] - __low2float(a2), v[5] - __high2float(a2));
    __half2 b3 = __floats2half2_rn(v[6] - __low2float(a3), v[7] - __high2float(a3));
    char* dst = xdst + n*ROWB + cw*2;
    *(uint4*)(dst)         = make_uint4(h2u(a0), h2u(a1), h2u(a2), h2u(a3));
    *(uint4*)(dst + PLANE) = make_uint4(h2u(b0), h2u(b1), h2u(b2), h2u(b3));
}
__device__ __forceinline__ void flush_csum(float* csum, float* gx, int lane) {
    #pragma unroll
    for (int j = 0; j < 8; j++) {
        float s = csum[j];
        s += __shfl_xor_sync(0xffffffffu, s, 16);
        s += __shfl_xor_sync(0xffffffffu, s, 8);
        s += __shfl_xor_sync(0xffffffffu, s, 4);
        s += __shfl_xor_sync(0xffffffffu, s, 2);
        s += __shfl_xor_sync(0xffffffffu, s, 1);
        if (lane == 0) atomicAdd(&gx[j], s);
    }
}

// -------------------------------------------------------------------------
// Persistent pipelined kernel: A-frags from L2 (no W smem, no W barrier),
// X double-buffered with converts interleaved under MMA blocks. 1 barrier/ct.
// -------------------------------------------------------------------------
__global__ void __launch_bounds__(256, 2)
qk_kernel(const float* __restrict__ x,
          const float* __restrict__ bq,
          const float* __restrict__ bk)
{
    extern __shared__ char smem[];
    const u32 smem_base = smem_u32(smem);
    float* q_s = (float*)smem;           // [64][130] fp32 (post-mma alias)
    float* k_s = (float*)smem + 8320;
    __shared__ unsigned item_s;

    const int tid  = threadIdx.x;
    const int lane = tid & 31;
    const int wid  = tid >> 5;
    const int wm = wid & 3;              // M slice: m in [32*wm, 32*wm+32)
    const int wn = wid >> 2;             // N slice: n in [64*wn, 64*wn+64)
    const int mbase = wm*32, nbase = wn*64;

    // ldmatrix per-lane byte offsets for B (plane-relative, invariant)
    u32 offB[8];
    #pragma unroll
    for (int nt = 0; nt < 8; nt++)
        offB[nt] = (u32)((nbase + nt*8 + (lane & 7))*ROWB + ((lane >> 3) & 1)*16);

    // bias for the q/k rows this thread writes
    const float* bsrc = (wm < 2) ? bq : bk;
    const int rq = lane >> 2;
    float bias0[2], bias1[2];
    #pragma unroll
    for (int mt = 0; mt < 2; mt++) {
        int r = (mbase & 63) + mt*16 + rq;
        bias0[mt] = bsrc[r];
        bias1[mt] = bsrc[r + 8];
    }

    const int cw = wid * 8;              // convert: 8 channels owned by this warp
    const int tx = tid & 15, ty = tid >> 4;
    const int o0 = ty * 4, p0 = tx * 4;  // logits tile

    while (true) {
        if (tid == 0) item_s = atomicAdd(&g_ctr, 1u);
        __syncthreads();                 // also: logits reads done before new writes
        const unsigned item = item_s;
        if (item >= NITEMS) break;
        const int b = item >> 5;
        const int n0g = (int)(item & 31) * NT;

        float acc[2][8][4];
        #pragma unroll
        for (int mt = 0; mt < 2; mt++)
            #pragma unroll
            for (int nt = 0; nt < 8; nt++)
                #pragma unroll
                for (int r = 0; r < 4; r++) acc[mt][nt][r] = 0.f;

        // ---- prologue: convert chunk 0 -> X0 (no W staging needed) ----
        {
            const float* xb0 = x + ((size_t)b*CC + (size_t)cw)*NPIX + n0g;
            char* x0p = smem + SM_X0;
            float csum[8] = {0,0,0,0,0,0,0,0};
            float va[8], vb[8];
            ldg_grp(va, xb0, 0, lane);
            ldg_grp(vb, xb0, 1, lane);
            proc_grp(va, x0p, 0, lane, cw, csum);
            ldg_grp(va, xb0, 2, lane);
            proc_grp(vb, x0p, 1, lane, cw, csum);
            ldg_grp(vb, xb0, 3, lane);
            proc_grp(va, x0p, 2, lane, cw, csum);
            proc_grp(vb, x0p, 3, lane, cw, csum);
            flush_csum(csum, &g_xsum[b*CC + cw], lane);
        }
        __syncthreads();

        // ---- main pipelined loop: 1 barrier per chunk ----
        for (int ct = 0; ct < CTILES; ++ct) {
            const bool more = (ct < CTILES-1);
            const u32 xcur = smem_base + ((ct & 1) ? SM_X1 : SM_X0);
            char* xnxt = smem + ((ct & 1) ? SM_X0 : SM_X1);
            const int ctn = more ? (ct + 1) : 0;
            const float* xbn = x + ((size_t)b*CC + (size_t)(ctn*CT + cw))*NPIX + n0g;
            // fragment bases for this chunk: (ct, plane p, warp slice wm)
            const uint4* fw0 = g_wfrag + (size_t)((ct*2 + 0)*4 + wm)*256;
            const uint4* fw1 = g_wfrag + (size_t)((ct*2 + 1)*4 + wm)*256;

            float csum[8] = {0,0,0,0,0,0,0,0};
            float va[8], vb[8];
            if (more) ldg_grp(va, xbn, 0, lane);

            // combo a0*x0
            mma_cb_frag(acc, fw0, xcur, offB, lane);
            if (more) { proc_grp(va, xnxt, 0, lane, cw, csum); ldg_grp(vb, xbn, 1, lane); }
            // combo a0*x1
            mma_cb_frag(acc, fw0, xcur + PLANE, offB, lane);
            if (more) { proc_grp(vb, xnxt, 1, lane, cw, csum); ldg_grp(va, xbn, 2, lane); }
            // combo a1*x0
            mma_cb_frag(acc, fw1, xcur, offB, lane);
            if (more) {
                proc_grp(va, xnxt, 2, lane, cw, csum);
                ldg_grp(vb, xbn, 3, lane);
                proc_grp(vb, xnxt, 3, lane, cw, csum);
                flush_csum(csum, &g_xsum[b*CC + ctn*CT + cw], lane);
            }
            __syncthreads();   // MMA(ct) smem reads done; X(ct+1) visible
        }

        // ---- q,k (+bias) -> smem [row][n] stride 130 ----
        {
            float* dst = (wm < 2) ? q_s : k_s;
            #pragma unroll
            for (int mt = 0; mt < 2; mt++) {
                const int r0 = (mbase & 63) + mt*16 + rq;
                #pragma unroll
                for (int nt = 0; nt < 8; nt++) {
                    const int col = nbase + nt*8 + (lane & 3)*2;
                    *(u64t*)&dst[r0*130 + col] =
                        pack2f(acc[mt][nt][0] + bias0[mt], acc[mt][nt][1] + bias0[mt]);
                    *(u64t*)&dst[(r0+8)*130 + col] =
                        pack2f(acc[mt][nt][2] + bias1[mt], acc[mt][nt][3] + bias1[mt]);
                }
            }
        }
        __syncthreads();

        // ---- logits += q @ k^T (packed f32x2 along n) ----
        u64t lacc[4][4];
        #pragma unroll
        for (int i = 0; i < 4; i++)
            #pragma unroll
            for (int j = 0; j < 4; j++) lacc[i][j] = 0ull;

        #pragma unroll 4
        for (int np = 0; np < NT/2; ++np) {
            u64t q2[4], k2[4];
            #pragma unroll
            for (int i = 0; i < 4; i++) q2[i] = *(const u64t*)&q_s[(o0+i)*130 + 2*np];
            #pragma unroll
            for (int j = 0; j < 4; j++) k2[j] = *(const u64t*)&k_s[(p0+j)*130 + 2*np];
            #pragma unroll
            for (int i = 0; i < 4; i++)
                #pragma unroll
                for (int j = 0; j < 4; j++)
                    lacc[i][j] = fma2(q2[i], k2[j], lacc[i][j]);
        }
        float* Lg = g_logits + b*C8*C8;
        #pragma unroll
        for (int i = 0; i < 4; i++)
            #pragma unroll
            for (int j = 0; j < 4; j++) {
                float lo, hi; unpack2(lacc[i][j], lo, hi);
                atomicAdd(&Lg[(o0+i)*C8 + p0 + j], lo + hi);
            }
        // loop-top __syncthreads guards smem reuse for next item
    }
}

// -------------------------------------------------------------------------
__global__ void finalize_kernel(const float* __restrict__ wv,
                                const float* __restrict__ bv,
                                float* __restrict__ out)
{
    __shared__ float vmean_s[C8];
    __shared__ float attn_s[C8][C8 + 1];
    const int b = blockIdx.x;
    const int t = threadIdx.x;  // 0..63

    const float* xs = g_xsum + b*CC;
    float acc = 0.f;
    for (int c = 0; c < CC; ++c) acc += wv[t*CC + c] * xs[c];
    vmean_s[t] = acc * (1.f / NPIX) + bv[t];

    const float* Lg = g_logits + b*C8*C8;
    float col[C8];
    float m = -1e30f;
    #pragma unroll
    for (int o = 0; o < C8; ++o) { col[o] = Lg[o*C8 + t]; m = fmaxf(m, col[o]); }
    float s = 0.f;
    #pragma unroll
    for (int o = 0; o < C8; ++o) { col[o] = expf(col[o] - m); s += col[o]; }
    float inv = 1.f / s;
    #pragma unroll
    for (int o = 0; o < C8; ++o) attn_s[o][t] = col[o] * inv;
    __syncthreads();

    float r = 0.f;
    #pragma unroll
    for (int p = 0; p < C8; ++p) r += attn_s[t][p] * vmean_s[p];
    out[b*C8 + t] = r;
}

// -------------------------------------------------------------------------
extern "C" void kernel_launch(void* const* d_in, const int* in_sizes, int n_in,
                              void* d_out, int out_size) {
    const float* x  = (const float*)d_in[0];
    const float* wq = (const float*)d_in[1];
    const float* bq = (const float*)d_in[2];
    const float* wk = (const float*)d_in[3];
    const float* bk = (const float*)d_in[4];
    const float* wv = (const float*)d_in[5];
    const float* bv = (const float*)d_in[6];
    float* out = (float*)d_out;

    cudaFuncSetAttribute(qk_kernel,
                         cudaFuncAttributeMaxDynamicSharedMemorySize, SMEM_BYTES);

    prep_kernel<<<256, 256>>>(wq, wk);
    qk_kernel<<<296, 256, SMEM_BYTES>>>(x, bq, bk);
    finalize_kernel<<<BB, C8>>>(wv, bv, out);
}

// round 15
// speedup vs baseline: 1.0168x; 1.0168x over previous
#include <cuda_runtime.h>
#include <cuda_fp16.h>

#define BB 32
#define CC 512
#define C8 64
#define NPIX 4096
#define NT 128
#define CT 64
#define CTILES 8
#define NITEMS (BB*(NPIX/NT))   // 1024

#define ROWB 144                 // padded row stride (bytes): conflict-free ldmatrix
#define PLANE (128*ROWB)         // 18432 B per fp16 plane tile
#define SM_X0 0                  // X buffer 0: 2 planes
#define SM_X1 36864              // X buffer 1: 2 planes
#define SMEM_BYTES 73728

typedef unsigned u32;
typedef unsigned long long u64t;
typedef unsigned short u16t;

// ---------------- helpers ----------------
__device__ __forceinline__ u32 smem_u32(const void* p) {
    u32 a; asm("{ .reg .u64 t; cvta.to.shared.u64 t, %1; cvt.u32.u64 %0, t; }" : "=r"(a) : "l"(p));
    return a;
}
__device__ __forceinline__ u64t pack2f(float lo, float hi) {
    u64t r; asm("mov.b64 %0, {%1, %2};" : "=l"(r) : "f"(lo), "f"(hi)); return r;
}
__device__ __forceinline__ u64t fma2(u64t a, u64t b, u64t c) {
    u64t d; asm("fma.rn.f32x2 %0, %1, %2, %3;" : "=l"(d) : "l"(a), "l"(b), "l"(c)); return d;
}
__device__ __forceinline__ void unpack2(u64t v, float& lo, float& hi) {
    asm("mov.b64 {%0, %1}, %2;" : "=f"(lo), "=f"(hi) : "l"(v));
}
__device__ __forceinline__ void ldsm4(u32* r, u32 addr) {
    asm volatile("ldmatrix.sync.aligned.m8n8.x4.shared.b16 {%0,%1,%2,%3}, [%4];"
        : "=r"(r[0]), "=r"(r[1]), "=r"(r[2]), "=r"(r[3]) : "r"(addr));
}
__device__ __forceinline__ void mma_f16(float* d, const u32* a, const u32* b) {
    asm volatile("mma.sync.aligned.m16n8k16.row.col.f32.f16.f16.f32 "
        "{%0,%1,%2,%3}, {%4,%5,%6,%7}, {%8,%9}, {%0,%1,%2,%3};"
        : "+f"(d[0]), "+f"(d[1]), "+f"(d[2]), "+f"(d[3])
        : "r"(a[0]), "r"(a[1]), "r"(a[2]), "r"(a[3]), "r"(b[0]), "r"(b[1]));
}
__device__ __forceinline__ u32 h2u(__half2 h) { return *reinterpret_cast<u32*>(&h); }

// ---------------- globals (no allocation allowed) ----------------
__device__ float g_logits[BB*C8*C8];
__device__ float g_xsum[BB*CC];
// A-fragment table: frag = ct<<6 | p<<5 | wm<<3 | ks<<1 | mt ; per frag 32 lanes x 16B
__device__ uint4 g_wfrag[512*32];     // 256 KB, L2-resident
__device__ unsigned g_ctr;

// -------------------------------------------------------------------------
// prep: zero accum + build fragment-ordered 2-limb fp16 W table.
// -------------------------------------------------------------------------
__global__ void prep_kernel(const float* __restrict__ wq,
                            const float* __restrict__ wk) {
    int t = blockIdx.x * blockDim.x + threadIdx.x;
    int S = gridDim.x * blockDim.x;
    if (t == 0) g_ctr = 0;
    for (int i = t; i < BB*C8*C8; i += S) g_logits[i] = 0.f;
    for (int i = t; i < BB*CC;    i += S) g_xsum[i]   = 0.f;
    u32* wf = (u32*)g_wfrag;
    const int total = 512*32*4;
    for (int idx = t; idx < total; idx += S) {
        int j    = idx & 3;
        int lane = (idx >> 2) & 31;
        int frag = idx >> 7;
        int mt = frag & 1;
        int ks = (frag >> 1) & 3;
        int wm = (frag >> 3) & 3;
        int p  = (frag >> 5) & 1;
        int ct = frag >> 6;
        int r    = wm*32 + mt*16 + (lane >> 2) + (j & 1)*8;
        int kloc = ks*16 + (lane & 3)*2 + (j >> 1)*8;
        int c    = ct*64 + kloc;
        float v0 = (r < 64) ? wq[r*CC + c]     : wk[(r-64)*CC + c];
        float v1 = (r < 64) ? wq[r*CC + c + 1] : wk[(r-64)*CC + c + 1];
        __half h0, h1;
        if (p == 0) {
            h0 = __float2half_rn(v0);
            h1 = __float2half_rn(v1);
        } else {
            h0 = __float2half_rn(v0 - __half2float(__float2half_rn(v0)));
            h1 = __float2half_rn(v1 - __half2float(__float2half_rn(v1)));
        }
        __half2 hh = __halves2half2(h0, h1);
        wf[idx] = h2u(hh);
    }
}

// convert pipeline pieces: each group = 1 pixel column slice (n = g*32+lane), 8 channels
__device__ __forceinline__ void ldg_grp(float* v, const float* xb, int g, int lane) {
    const int n = g*32 + lane;
    #pragma unroll
    for (int j = 0; j < 8; j++) v[j] = xb[(size_t)j*NPIX + n];
}
__device__ __forceinline__ void proc_grp(const float* v, char* xdst, int g, int lane,
                                         int cw, float* csum) {
    const int n = g*32 + lane;
    #pragma unroll
    for (int j = 0; j < 8; j++) csum[j] += v[j];
    __half2 a0 = __floats2half2_rn(v[0], v[1]);
    __half2 a1 = __floats2half2_rn(v[2], v[3]);
    __half2 a2 = __floats2half2_rn(v[4], v[5]);
    __half2 a3 = __floats2half2_rn(v[6], v[7]);
    __half2 b0 = __floats2half2_rn(v[0] - __low2float(a0), v[1] - __high2float(a0));
    __half2 b1 = __floats2half2_rn(v[2] - __low2float(a1), v[3] - __high2float(a1));
    __half2 b2 = __floats2half2_rn(v[4] - __low2float(a2), v[5] - __high2float(a2));
    __half2 b3 = __floats2half2_rn(v[6] - __low2float(a3), v[7] - __high2float(a3));
    char* dst = xdst + n*ROWB + cw*2;
    *(uint4*)(dst)         = make_uint4(h2u(a0), h2u(a1), h2u(a2), h2u(a3));
    *(uint4*)(dst + PLANE) = make_uint4(h2u(b0), h2u(b1), h2u(b2), h2u(b3));
}
__device__ __forceinline__ void flush_csum(float* csum, float* gx, int lane) {
    #pragma unroll
    for (int j = 0; j < 8; j++) {
        float s = csum[j];
        s += __shfl_xor_sync(0xffffffffu, s, 16);
        s += __shfl_xor_sync(0xffffffffu, s, 8);
        s += __shfl_xor_sync(0xffffffffu, s, 4);
        s += __shfl_xor_sync(0xffffffffu, s, 2);
        s += __shfl_xor_sync(0xffffffffu, s, 1);
        if (lane == 0) atomicAdd(&gx[j], s);
    }
}

// -------------------------------------------------------------------------
// Persistent pipelined kernel: A-frags from L2, B via ldsm.x4 (2 nt per load),
// 12 flattened ks-units per chunk with converts spread across units 0..8.
// -------------------------------------------------------------------------
__global__ void __launch_bounds__(256, 2)
qk_kernel(const float* __restrict__ x,
          const float* __restrict__ bq,
          const float* __restrict__ bk)
{
    extern __shared__ char smem[];
    const u32 smem_base = smem_u32(smem);
    float* q_s = (float*)smem;           // [64][130] fp32 (post-mma alias)
    float* k_s = (float*)smem + 8320;
    __shared__ unsigned item_s;

    const int tid  = threadIdx.x;
    const int lane = tid & 31;
    const int wid  = tid >> 5;
    const int wm = wid & 3;              // M slice: m in [32*wm, 32*wm+32)
    const int wn = wid >> 2;             // N slice: n in [64*wn, 64*wn+64)
    const int mbase = wm*32, nbase = wn*64;

    // x4 B offsets: quad t covers nt pair (2t, 2t+1):
    // lanes 0-7: nt=2t rows k0-7 | 8-15: k8-15 | 16-23: nt=2t+1 k0-7 | 24-31: k8-15
    u32 offB4[4];
    #pragma unroll
    for (int t = 0; t < 4; t++)
        offB4[t] = (u32)((nbase + (2*t + ((lane >> 4) & 1))*8 + (lane & 7))*ROWB
                         + ((lane >> 3) & 1)*16);

    // bias for the q/k rows this thread writes
    const float* bsrc = (wm < 2) ? bq : bk;
    const int rq = lane >> 2;
    float bias0[2], bias1[2];
    #pragma unroll
    for (int mt = 0; mt < 2; mt++) {
        int r = (mbase & 63) + mt*16 + rq;
        bias0[mt] = bsrc[r];
        bias1[mt] = bsrc[r + 8];
    }

    const int cw = wid * 8;              // convert: 8 channels owned by this warp
    const int tx = tid & 15, ty = tid >> 4;
    const int o0 = ty * 4, p0 = tx * 4;  // logits tile

    while (true) {
        if (tid == 0) item_s = atomicAdd(&g_ctr, 1u);
        __syncthreads();                 // also: logits reads done before new writes
        const unsigned item = item_s;
        if (item >= NITEMS) break;
        const int b = item >> 5;
        const int n0g = (int)(item & 31) * NT;

        float acc[2][8][4];
        #pragma unroll
        for (int mt = 0; mt < 2; mt++)
            #pragma unroll
            for (int nt = 0; nt < 8; nt++)
                #pragma unroll
                for (int r = 0; r < 4; r++) acc[mt][nt][r] = 0.f;

        // ---- prologue: convert chunk 0 -> X0 ----
        {
            const float* xb0 = x + ((size_t)b*CC + (size_t)cw)*NPIX + n0g;
            char* x0p = smem + SM_X0;
            float csum[8] = {0,0,0,0,0,0,0,0};
            float va[8], vb[8];
            ldg_grp(va, xb0, 0, lane);
            ldg_grp(vb, xb0, 1, lane);
            proc_grp(va, x0p, 0, lane, cw, csum);
            ldg_grp(va, xb0, 2, lane);
            proc_grp(vb, x0p, 1, lane, cw, csum);
            ldg_grp(vb, xb0, 3, lane);
            proc_grp(va, x0p, 2, lane, cw, csum);
            proc_grp(vb, x0p, 3, lane, cw, csum);
            flush_csum(csum, &g_xsum[b*CC + cw], lane);
        }
        __syncthreads();

        // ---- main pipelined loop: 12 ks-units per chunk, 1 barrier/chunk ----
        for (int ct = 0; ct < CTILES; ++ct) {
            const bool more = (ct < CTILES-1);
            const u32 xcur = smem_base + ((ct & 1) ? SM_X1 : SM_X0);
            char* xnxt = smem + ((ct & 1) ? SM_X0 : SM_X1);
            const int ctn = more ? (ct + 1) : 0;
            const float* xbn = x + ((size_t)b*CC + (size_t)(ctn*CT + cw))*NPIX + n0g;
            const uint4* fw0 = g_wfrag + (size_t)((ct*2 + 0)*4 + wm)*256;
            const uint4* fw1 = g_wfrag + (size_t)((ct*2 + 1)*4 + wm)*256;

            float csum[8] = {0,0,0,0,0,0,0,0};
            float va[8], vb[8];

            uint4 fA[2][2];
            fA[0][0] = fw0[lane];
            fA[0][1] = fw0[32 + lane];

            #pragma unroll
            for (int u = 0; u < 12; u++) {
                const int cur = u & 1, nxt = cur ^ 1;
                // prefetch A-frags for the next ks-unit
                if (u < 11) {
                    const int un = u + 1;
                    const uint4* f = (un >> 2) == 2 ? fw1 : fw0;
                    const int ksn = un & 3;
                    fA[nxt][0] = f[ksn*64 + lane];
                    fA[nxt][1] = f[ksn*64 + 32 + lane];
                }
                const int cb = u >> 2, ks = u & 3;
                const u32 baseB = xcur + ((cb == 1) ? PLANE : 0);
                const u32* aC0 = (const u32*)&fA[cur][0];
                const u32* aC1 = (const u32*)&fA[cur][1];
                #pragma unroll
                for (int h = 0; h < 2; h++) {
                    u32 r0[4], r1[4];
                    ldsm4(r0, baseB + offB4[2*h]     + ks*32);   // nt 4h+0, 4h+1
                    ldsm4(r1, baseB + offB4[2*h + 1] + ks*32);   // nt 4h+2, 4h+3
                    mma_f16(acc[0][4*h+0], aC0, &r0[0]); mma_f16(acc[1][4*h+0], aC1, &r0[0]);
                    mma_f16(acc[0][4*h+1], aC0, &r0[2]); mma_f16(acc[1][4*h+1], aC1, &r0[2]);
                    mma_f16(acc[0][4*h+2], aC0, &r1[0]); mma_f16(acc[1][4*h+2], aC1, &r1[0]);
                    mma_f16(acc[0][4*h+3], aC0, &r1[2]); mma_f16(acc[1][4*h+3], aC1, &r1[2]);
                }
                // interleaved convert units for chunk ct+1
                if (more) {
                    if (u == 0) ldg_grp(va, xbn, 0, lane);
                    if (u == 1) { proc_grp(va, xnxt, 0, lane, cw, csum); }
                    if (u == 2) ldg_grp(vb, xbn, 1, lane);
                    if (u == 3) { proc_grp(vb, xnxt, 1, lane, cw, csum); }
                    if (u == 4) ldg_grp(va, xbn, 2, lane);
                    if (u == 5) { proc_grp(va, xnxt, 2, lane, cw, csum); }
                    if (u == 6) ldg_grp(vb, xbn, 3, lane);
                    if (u == 7) { proc_grp(vb, xnxt, 3, lane, cw, csum); }
                    if (u == 8) flush_csum(csum, &g_xsum[b*CC + ctn*CT + cw], lane);
                }
            }
            __syncthreads();   // MMA(ct) smem reads done; X(ct+1) visible
        }

        // ---- q,k (+bias) -> smem [row][n] stride 130 ----
        {
            float* dst = (wm < 2) ? q_s : k_s;
            #pragma unroll
            for (int mt = 0; mt < 2; mt++) {
                const int r0 = (mbase & 63) + mt*16 + rq;
                #pragma unroll
                for (int nt = 0; nt < 8; nt++) {
                    const int col = nbase + nt*8 + (lane & 3)*2;
                    *(u64t*)&dst[r0*130 + col] =
                        pack2f(acc[mt][nt][0] + bias0[mt], acc[mt][nt][1] + bias0[mt]);
                    *(u64t*)&dst[(r0+8)*130 + col] =
                        pack2f(acc[mt][nt][2] + bias1[mt], acc[mt][nt][3] + bias1[mt]);
                }
            }
        }
        __syncthreads();

        // ---- logits += q @ k^T (packed f32x2 along n) ----
        u64t lacc[4][4];
        #pragma unroll
        for (int i = 0; i < 4; i++)
            #pragma unroll
            for (int j = 0; j < 4; j++) lacc[i][j] = 0ull;

        #pragma unroll 4
        for (int np = 0; np < NT/2; ++np) {
            u64t q2[4], k2[4];
            #pragma unroll
            for (int i = 0; i < 4; i++) q2[i] = *(const u64t*)&q_s[(o0+i)*130 + 2*np];
            #pragma unroll
            for (int j = 0; j < 4; j++) k2[j] = *(const u64t*)&k_s[(p0+j)*130 + 2*np];
            #pragma unroll
            for (int i = 0; i < 4; i++)
                #pragma unroll
                for (int j = 0; j < 4; j++)
                    lacc[i][j] = fma2(q2[i], k2[j], lacc[i][j]);
        }
        float* Lg = g_logits + b*C8*C8;
        #pragma unroll
        for (int i = 0; i < 4; i++)
            #pragma unroll
            for (int j = 0; j < 4; j++) {
                float lo, hi; unpack2(lacc[i][j], lo, hi);
                atomicAdd(&Lg[(o0+i)*C8 + p0 + j], lo + hi);
            }
        // loop-top __syncthreads guards smem reuse for next item
    }
}

// -------------------------------------------------------------------------
__global__ void finalize_kernel(const float* __restrict__ wv,
                                const float* __restrict__ bv,
                                float* __restrict__ out)
{
    __shared__ float vmean_s[C8];
    __shared__ float attn_s[C8][C8 + 1];
    const int b = blockIdx.x;
    const int t = threadIdx.x;  // 0..63

    const float* xs = g_xsum + b*CC;
    float acc = 0.f;
    for (int c = 0; c < CC; ++c) acc += wv[t*CC + c] * xs[c];
    vmean_s[t] = acc * (1.f / NPIX) + bv[t];

    const float* Lg = g_logits + b*C8*C8;
    float col[C8];
    float m = -1e30f;
    #pragma unroll
    for (int o = 0; o < C8; ++o) { col[o] = Lg[o*C8 + t]; m = fmaxf(m, col[o]); }
    float s = 0.f;
    #pragma unroll
    for (int o = 0; o < C8; ++o) { col[o] = expf(col[o] - m); s += col[o]; }
    float inv = 1.f / s;
    #pragma unroll
    for (int o = 0; o < C8; ++o) attn_s[o][t] = col[o] * inv;
    __syncthreads();

    float r = 0.f;
    #pragma unroll
    for (int p = 0; p < C8; ++p) r += attn_s[t][p] * vmean_s[p];
    out[b*C8 + t] = r;
}

// -------------------------------------------------------------------------
extern "C" void kernel_launch(void* const* d_in, const int* in_sizes, int n_in,
                              void* d_out, int out_size) {
    const float* x  = (const float*)d_in[0];
    const float* wq = (const float*)d_in[1];
    const float* bq = (const float*)d_in[2];
    const float* wk = (const float*)d_in[3];
    const float* bk = (const float*)d_in[4];
    const float* wv = (const float*)d_in[5];
    const float* bv = (const float*)d_in[6];
    float* out = (float*)d_out;

    cudaFuncSetAttribute(qk_kernel,
                         cudaFuncAttributeMaxDynamicSharedMemorySize, SMEM_BYTES);

    prep_kernel<<<256, 256>>>(wq, wk);
    qk_kernel<<<296, 256, SMEM_BYTES>>>(x, bq, bk);
    finalize_kernel<<<BB, C8>>>(wv, bv, out);
}